// round 16
// baseline (speedup 1.0000x reference)
#include <cuda_runtime.h>
#include <cuda_bf16.h>
#include <stdint.h>

#define B_ 8
#define C_ 256
#define T_ 4
#define N_ 4096
#define H_ 1024
#define L_ 16384   // T_*N_

// ---------------- scratch (device globals: no allocation allowed) ----------------
__device__ __nv_bfloat16 g_s1[(size_t)B_ * C_ * L_];   //  64 MB spikes after LIF1
__device__ __nv_bfloat16 g_s2[(size_t)B_ * H_ * L_];   // 256 MB spikes after LIF2
__device__ __nv_bfloat16 g_w1hi[H_ * C_];
__device__ __nv_bfloat16 g_w1mid[H_ * C_];
__device__ __nv_bfloat16 g_w1lo[H_ * C_];
__device__ __nv_bfloat16 g_w2hi[C_ * H_];
__device__ __nv_bfloat16 g_w2lo[C_ * H_];
__device__ float g_inv1[H_], g_add1[H_];
__device__ float g_inv2[C_], g_add2[C_];

// ---------------- small PTX helpers ------------------------------------------------
__device__ __forceinline__ uint32_t smem_u32(const void* p) {
  return (uint32_t)__cvta_generic_to_shared(p);
}
__device__ __forceinline__ void cp16(uint32_t dst, const void* src) {
  asm volatile("cp.async.cg.shared.global [%0], [%1], 16;\n" :: "r"(dst), "l"(src));
}
__device__ __forceinline__ void cp_commit() { asm volatile("cp.async.commit_group;\n"); }
__device__ __forceinline__ void cp_wait1() {
  asm volatile("cp.async.wait_group 1;\n" ::: "memory");
}
__device__ __forceinline__ void ldsmx4(uint32_t r[4], uint32_t a) {
  asm volatile("ldmatrix.sync.aligned.m8n8.x4.shared.b16 {%0,%1,%2,%3}, [%4];\n"
               : "=r"(r[0]), "=r"(r[1]), "=r"(r[2]), "=r"(r[3]) : "r"(a));
}
__device__ __forceinline__ void ldsmx4t(uint32_t r[4], uint32_t a) {
  asm volatile("ldmatrix.sync.aligned.m8n8.x4.trans.shared.b16 {%0,%1,%2,%3}, [%4];\n"
               : "=r"(r[0]), "=r"(r[1]), "=r"(r[2]), "=r"(r[3]) : "r"(a));
}
__device__ __forceinline__ void mma16816(float c[4], const uint32_t a[4], const uint32_t b[2]) {
  asm volatile(
      "mma.sync.aligned.m16n8k16.row.col.f32.bf16.bf16.f32 "
      "{%0,%1,%2,%3}, {%4,%5,%6,%7}, {%8,%9}, {%0,%1,%2,%3};\n"
      : "+f"(c[0]), "+f"(c[1]), "+f"(c[2]), "+f"(c[3])
      : "r"(a[0]), "r"(a[1]), "r"(a[2]), "r"(a[3]), "r"(b[0]), "r"(b[1]));
}

// ---------------- prep: weight split + BN folding (double-precision constants) ----
__global__ void prep_kernel(const float* __restrict__ fc1_w, const float* __restrict__ fc2_w,
                            const float* __restrict__ bn1_g, const float* __restrict__ bn1_b,
                            const float* __restrict__ bn1_m, const float* __restrict__ bn1_v,
                            const float* __restrict__ bn2_g, const float* __restrict__ bn2_b,
                            const float* __restrict__ bn2_m, const float* __restrict__ bn2_v) {
  int i = blockIdx.x * blockDim.x + threadIdx.x;
  if (i < H_ * C_) {
    float w = fc1_w[i];
    __nv_bfloat16 hi = __float2bfloat16(w);
    float r1 = w - __bfloat162float(hi);
    __nv_bfloat16 mid = __float2bfloat16(r1);
    float r2 = r1 - __bfloat162float(mid);
    g_w1hi[i] = hi;
    g_w1mid[i] = mid;
    g_w1lo[i] = __float2bfloat16(r2);
    float w2 = fc2_w[i];
    __nv_bfloat16 hi2 = __float2bfloat16(w2);
    g_w2hi[i] = hi2;
    g_w2lo[i] = __float2bfloat16(w2 - __bfloat162float(hi2));
  }
  if (i < H_) {
    float vpe = bn1_v[i] + 1e-5f;
    float inv = (float)((double)bn1_g[i] / sqrt((double)vpe));
    g_inv1[i] = inv;
    g_add1[i] = bn1_b[i] - bn1_m[i] * inv;
  }
  if (i < C_) {
    float vpe = bn2_v[i] + 1e-5f;
    float inv = (float)((double)bn2_g[i] / sqrt((double)vpe));
    g_inv2[i] = inv;
    g_add2[i] = bn2_b[i] - bn2_m[i] * inv;
  }
}

// ---------------- stage 1: bn2 + LIF over T -> binary spikes (bf16) --------------
__global__ void lif1_kernel(const float* __restrict__ x) {
  int idx = blockIdx.x * blockDim.x + threadIdx.x;   // over B*C*N (exact grid)
  int n  = idx & (N_ - 1);
  int bc = idx >> 12;
  int c  = bc & (C_ - 1);
  float inv = g_inv2[c], add = g_add2[c];
  size_t base = (size_t)bc * L_ + n;
  float v = 0.0f;
#pragma unroll
  for (int t = 0; t < T_; t++) {
    float xt = x[base + t * N_] * inv + add;
    v = v + __fdiv_rn(xt - v, 1.5f);
    float s = (v >= 1.0f) ? 1.0f : 0.0f;
    g_s1[base + t * N_] = __float2bfloat16(s);
    v = (s != 0.0f) ? 0.0f : v;
  }
}

// ==================================================================================
// stage 2: fc1 GEMM (triple split, K=256 resident) + bias + bn1 + LIF fused
// Block 64(m) x 256(n), 8 warps (2m x 4n), warp tile 32x64.
// B tiles [k32][n256] triple-buffered (depth-3 cp.async, wait_group 1).
// ==================================================================================
#define F1_SA 264                       // A row stride (256 + 8), elements
#define F1_SB 264                       // B row stride (256 + 8), elements
#define F1_ASIZE (64 * F1_SA)           // per split, elements
#define F1_BSIZE (32 * F1_SB)           // per buffer, elements
#define F1_SMEM ((3 * F1_ASIZE + 3 * F1_BSIZE) * 2)

__global__ void __launch_bounds__(256, 1) fc1_lif_kernel(const float* __restrict__ fc1_b) {
  extern __shared__ __nv_bfloat16 sm1[];
  __nv_bfloat16* As = sm1;                    // [3][64][F1_SA]
  __nv_bfloat16* Bs = sm1 + 3 * F1_ASIZE;     // [3][32][F1_SB]

  const int tid = threadIdx.x;
  const int b = blockIdx.z, h0 = blockIdx.y * 64, n0 = blockIdx.x * 256;
  const int warp = tid >> 5, lane = tid & 31;
  const int wm = warp >> 2, wn = warp & 3;
  const int g = lane >> 2, tq = lane & 3;

  // ---- stage full-K A (hi, mid, lo) once via cp.async (joins group 0) ----
  {
    const __nv_bfloat16* srcs[3] = {g_w1hi, g_w1mid, g_w1lo};
#pragma unroll
    for (int s = 0; s < 3; s++)
#pragma unroll
      for (int i = 0; i < 8; i++) {
        int lin = tid + i * 256;              // 64 rows x 32 (16B) segs
        int r = lin >> 5, sg = lin & 31;
        cp16(smem_u32(&As[s * F1_ASIZE + r * F1_SA + sg * 8]),
             &srcs[s][(h0 + r) * C_ + sg * 8]);
      }
  }

  auto stageB = [&](int j, int buf) {
    int t = j >> 3, kt = j & 7;
    size_t base = (size_t)(b * C_ + kt * 32) * L_ + (size_t)t * N_ + n0;
#pragma unroll
    for (int i = 0; i < 4; i++) {
      int lin = tid + i * 256;                // 32 rows x 32 segs
      int r = lin >> 5, sg = lin & 31;
      cp16(smem_u32(&Bs[buf * F1_BSIZE + r * F1_SB + sg * 8]),
           &g_s1[base + (size_t)r * L_ + sg * 8]);
    }
  };

  stageB(0, 0);
  cp_commit();          // group: A + B0
  stageB(1, 1);
  cp_commit();          // group: B1

  float acc[2][8][4];
  float v[2][8][4];
#pragma unroll
  for (int mt = 0; mt < 2; mt++)
#pragma unroll
    for (int nt = 0; nt < 8; nt++)
#pragma unroll
      for (int q = 0; q < 4; q++) { acc[mt][nt][q] = 0.0f; v[mt][nt][q] = 0.0f; }

  const uint32_t a_base = smem_u32(&As[(wm * 32 + (lane & 15)) * F1_SA + (lane >> 4) * 8]);
  const uint32_t b_base = smem_u32(&Bs[(lane & 15) * F1_SB + wn * 64 + (lane >> 4) * 8]);

  int buf = 0;
#pragma unroll 1
  for (int j = 0; j < 32; j++) {
    cp_wait1();                       // stage j complete (j+1 may be in flight)
    __syncthreads();
    int nb = buf + 2; if (nb >= 3) nb -= 3;
    if (j + 2 < 32) stageB(j + 2, nb);
    cp_commit();                      // unconditional: keeps group accounting exact

    const int kt = j & 7;
#pragma unroll
    for (int ks = 0; ks < 2; ks++) {
      uint32_t bf[8][2];
#pragma unroll
      for (int p = 0; p < 4; p++) {
        uint32_t r[4];
        ldsmx4t(r, b_base + (uint32_t)(buf * F1_BSIZE + ks * 16 * F1_SB + p * 16) * 2);
        bf[2 * p][0] = r[0]; bf[2 * p][1] = r[1];
        bf[2 * p + 1][0] = r[2]; bf[2 * p + 1][1] = r[3];
      }
#pragma unroll
      for (int mt = 0; mt < 2; mt++)
#pragma unroll
        for (int s = 0; s < 3; s++) {
          uint32_t a[4];
          ldsmx4(a, a_base + (uint32_t)(s * F1_ASIZE + mt * 16 * F1_SA + kt * 32 + ks * 16) * 2);
#pragma unroll
          for (int nt = 0; nt < 8; nt++) mma16816(acc[mt][nt], a, bf[nt]);
        }
    }

    if ((j & 7) == 7) {            // end of one timestep: fused bias+bn1+LIF epilogue
      const int t = j >> 3;
#pragma unroll
      for (int mt = 0; mt < 2; mt++)
#pragma unroll
        for (int rr = 0; rr < 2; rr++) {
          int row = h0 + wm * 32 + mt * 16 + rr * 8 + g;
          float bias = fc1_b[row], inv = g_inv1[row], add = g_add1[row];
          size_t obase = (size_t)(b * H_ + row) * L_ + (size_t)t * N_;
#pragma unroll
          for (int nt = 0; nt < 8; nt++) {
            int col = n0 + wn * 64 + nt * 8 + tq * 2;
            float z0 = (acc[mt][nt][rr * 2 + 0] + bias) * inv + add;
            float z1 = (acc[mt][nt][rr * 2 + 1] + bias) * inv + add;
            float v0 = v[mt][nt][rr * 2 + 0];
            float v1 = v[mt][nt][rr * 2 + 1];
            v0 = v0 + __fdiv_rn(z0 - v0, 1.5f);
            v1 = v1 + __fdiv_rn(z1 - v1, 1.5f);
            float s0 = (v0 >= 1.0f) ? 1.0f : 0.0f;
            float s1 = (v1 >= 1.0f) ? 1.0f : 0.0f;
            v[mt][nt][rr * 2 + 0] = (s0 != 0.0f) ? 0.0f : v0;
            v[mt][nt][rr * 2 + 1] = (s1 != 0.0f) ? 0.0f : v1;
            __nv_bfloat162 sp;
            sp.x = __float2bfloat16(s0);
            sp.y = __float2bfloat16(s1);
            *(__nv_bfloat162*)&g_s2[obase + col] = sp;
            acc[mt][nt][rr * 2 + 0] = 0.0f;
            acc[mt][nt][rr * 2 + 1] = 0.0f;
          }
        }
    }
    buf = (buf == 2) ? 0 : buf + 1;
  }
}

// ==================================================================================
// stage 3: fc2 GEMM (double split) + bias -> fp32 output
// Block 64(m=c) x 256(n=l), 8 warps (2m x 4n), warp tile 32x64.
// A and B tiles triple-buffered (depth-3 cp.async, wait_group 1).
// ==================================================================================
#define F2_SA 40                        // A row stride (32 + 8), elements
#define F2_SB 264                       // B row stride (256 + 8), elements
#define F2_ABUF (2 * 64 * F2_SA)        // per buffer (2 splits), elements
#define F2_BBUF (32 * F2_SB)            // per buffer, elements
#define F2_SMEM ((3 * F2_ABUF + 3 * F2_BBUF) * 2)

__global__ void __launch_bounds__(256, 2) fc2_kernel(const float* __restrict__ fc2_b,
                                                     float* __restrict__ out) {
  extern __shared__ __nv_bfloat16 sm2[];
  __nv_bfloat16* As = sm2;                    // [3buf][2split][64][F2_SA]
  __nv_bfloat16* Bs = sm2 + 3 * F2_ABUF;      // [3buf][32][F2_SB]

  const int tid = threadIdx.x;
  const int b = blockIdx.z, c0 = blockIdx.y * 64, l0 = blockIdx.x * 256;
  const int warp = tid >> 5, lane = tid & 31;
  const int wm = warp >> 2, wn = warp & 3;
  const int g = lane >> 2, tq = lane & 3;

  auto stage = [&](int kt, int buf) {
    int r = tid >> 2, sg = tid & 3;           // A: 64 rows x 4 segs, per split
    cp16(smem_u32(&As[buf * F2_ABUF + r * F2_SA + sg * 8]),
         &g_w2hi[(c0 + r) * H_ + kt * 32 + sg * 8]);
    cp16(smem_u32(&As[buf * F2_ABUF + 64 * F2_SA + r * F2_SA + sg * 8]),
         &g_w2lo[(c0 + r) * H_ + kt * 32 + sg * 8]);
    size_t base = (size_t)(b * H_ + kt * 32) * L_ + l0;
#pragma unroll
    for (int i = 0; i < 4; i++) {
      int lin = tid + i * 256;                // B: 32 rows x 32 segs
      int rb = lin >> 5, sgb = lin & 31;
      cp16(smem_u32(&Bs[buf * F2_BBUF + rb * F2_SB + sgb * 8]),
           &g_s2[base + (size_t)rb * L_ + sgb * 8]);
    }
  };

  stage(0, 0);
  cp_commit();
  stage(1, 1);
  cp_commit();

  float acc[2][8][4];
#pragma unroll
  for (int mt = 0; mt < 2; mt++)
#pragma unroll
    for (int nt = 0; nt < 8; nt++)
#pragma unroll
      for (int q = 0; q < 4; q++) acc[mt][nt][q] = 0.0f;

  const uint32_t a_base = smem_u32(&As[(wm * 32 + (lane & 15)) * F2_SA + (lane >> 4) * 8]);
  const uint32_t b_base = smem_u32(&Bs[(lane & 15) * F2_SB + wn * 64 + (lane >> 4) * 8]);

  int buf = 0;
#pragma unroll 1
  for (int j = 0; j < 32; j++) {
    cp_wait1();
    __syncthreads();
    int nb = buf + 2; if (nb >= 3) nb -= 3;
    if (j + 2 < 32) stage(j + 2, nb);
    cp_commit();

#pragma unroll
    for (int ks = 0; ks < 2; ks++) {
      uint32_t bf[8][2];
#pragma unroll
      for (int p = 0; p < 4; p++) {
        uint32_t r[4];
        ldsmx4t(r, b_base + (uint32_t)(buf * F2_BBUF + ks * 16 * F2_SB + p * 16) * 2);
        bf[2 * p][0] = r[0]; bf[2 * p][1] = r[1];
        bf[2 * p + 1][0] = r[2]; bf[2 * p + 1][1] = r[3];
      }
#pragma unroll
      for (int mt = 0; mt < 2; mt++)
#pragma unroll
        for (int s = 0; s < 2; s++) {
          uint32_t a[4];
          ldsmx4(a, a_base + (uint32_t)(buf * F2_ABUF + s * 64 * F2_SA + mt * 16 * F2_SA + ks * 16) * 2);
#pragma unroll
          for (int nt = 0; nt < 8; nt++) mma16816(acc[mt][nt], a, bf[nt]);
        }
    }
    buf = (buf == 2) ? 0 : buf + 1;
  }

  // epilogue: bias + coalesced float2 stores
#pragma unroll
  for (int mt = 0; mt < 2; mt++)
#pragma unroll
    for (int rr = 0; rr < 2; rr++) {
      int row = c0 + wm * 32 + mt * 16 + rr * 8 + g;
      float bias = fc2_b[row];
      size_t obase = (size_t)(b * C_ + row) * L_ + l0;
#pragma unroll
      for (int nt = 0; nt < 8; nt++) {
        int col = wn * 64 + nt * 8 + tq * 2;
        float2 o;
        o.x = acc[mt][nt][rr * 2 + 0] + bias;
        o.y = acc[mt][nt][rr * 2 + 1] + bias;
        *(float2*)&out[obase + col] = o;
      }
    }
}

// ---------------- launch ----------------------------------------------------------
extern "C" void kernel_launch(void* const* d_in, const int* in_sizes, int n_in,
                              void* d_out, int out_size) {
  (void)in_sizes; (void)n_in; (void)out_size;
  const float* x      = (const float*)d_in[0];
  const float* fc1_w  = (const float*)d_in[1];
  const float* fc1_b  = (const float*)d_in[2];
  const float* fc2_w  = (const float*)d_in[3];
  const float* fc2_b  = (const float*)d_in[4];
  const float* bn1_g  = (const float*)d_in[5];
  const float* bn1_bt = (const float*)d_in[6];
  const float* bn1_m  = (const float*)d_in[7];
  const float* bn1_v  = (const float*)d_in[8];
  const float* bn2_g  = (const float*)d_in[9];
  const float* bn2_bt = (const float*)d_in[10];
  const float* bn2_m  = (const float*)d_in[11];
  const float* bn2_v  = (const float*)d_in[12];
  float* out = (float*)d_out;

  prep_kernel<<<(H_ * C_) / 256, 256>>>(fc1_w, fc2_w, bn1_g, bn1_bt, bn1_m, bn1_v,
                                        bn2_g, bn2_bt, bn2_m, bn2_v);
  lif1_kernel<<<(B_ * C_ * N_) / 256, 256>>>(x);

  static bool attr_set = false;
  if (!attr_set) {
    cudaFuncSetAttribute(fc1_lif_kernel, cudaFuncAttributeMaxDynamicSharedMemorySize, F1_SMEM);
    cudaFuncSetAttribute(fc2_kernel, cudaFuncAttributeMaxDynamicSharedMemorySize, F2_SMEM);
    attr_set = true;
  }

  dim3 g2(N_ / 256, H_ / 64, B_);
  fc1_lif_kernel<<<g2, 256, F1_SMEM>>>(fc1_b);

  dim3 g3(L_ / 256, C_ / 64, B_);
  fc2_kernel<<<g3, 256, F2_SMEM>>>(fc2_b, out);
}

// round 17
// speedup vs baseline: 1.0011x; 1.0011x over previous
#include <cuda_runtime.h>
#include <cuda_bf16.h>
#include <stdint.h>

#define B_ 8
#define C_ 256
#define T_ 4
#define N_ 4096
#define H_ 1024
#define L_ 16384   // T_*N_

// ---------------- scratch (device globals: no allocation allowed) ----------------
__device__ __nv_bfloat16 g_s1[(size_t)B_ * C_ * L_];   //  64 MB spikes after LIF1
__device__ __nv_bfloat16 g_s2[(size_t)B_ * H_ * L_];   // 256 MB spikes after LIF2
__device__ __nv_bfloat16 g_w1hi[H_ * C_];
__device__ __nv_bfloat16 g_w1mid[H_ * C_];
__device__ __nv_bfloat16 g_w1lo[H_ * C_];
__device__ __nv_bfloat16 g_w2hi[C_ * H_];
__device__ __nv_bfloat16 g_w2lo[C_ * H_];
__device__ float g_inv1[H_], g_add1[H_];
__device__ float g_inv2[C_], g_add2[C_];

// ---------------- small PTX helpers ------------------------------------------------
__device__ __forceinline__ uint32_t smem_u32(const void* p) {
  return (uint32_t)__cvta_generic_to_shared(p);
}
__device__ __forceinline__ void cp16(uint32_t dst, const void* src) {
  asm volatile("cp.async.cg.shared.global [%0], [%1], 16;\n" :: "r"(dst), "l"(src));
}
__device__ __forceinline__ void cp_commit() { asm volatile("cp.async.commit_group;\n"); }
__device__ __forceinline__ void cp_wait1() {
  asm volatile("cp.async.wait_group 1;\n" ::: "memory");
}
__device__ __forceinline__ void ldsmx4(uint32_t r[4], uint32_t a) {
  asm volatile("ldmatrix.sync.aligned.m8n8.x4.shared.b16 {%0,%1,%2,%3}, [%4];\n"
               : "=r"(r[0]), "=r"(r[1]), "=r"(r[2]), "=r"(r[3]) : "r"(a));
}
__device__ __forceinline__ void ldsmx4t(uint32_t r[4], uint32_t a) {
  asm volatile("ldmatrix.sync.aligned.m8n8.x4.trans.shared.b16 {%0,%1,%2,%3}, [%4];\n"
               : "=r"(r[0]), "=r"(r[1]), "=r"(r[2]), "=r"(r[3]) : "r"(a));
}
__device__ __forceinline__ void mma16816(float c[4], const uint32_t a[4], const uint32_t b[2]) {
  asm volatile(
      "mma.sync.aligned.m16n8k16.row.col.f32.bf16.bf16.f32 "
      "{%0,%1,%2,%3}, {%4,%5,%6,%7}, {%8,%9}, {%0,%1,%2,%3};\n"
      : "+f"(c[0]), "+f"(c[1]), "+f"(c[2]), "+f"(c[3])
      : "r"(a[0]), "r"(a[1]), "r"(a[2]), "r"(a[3]), "r"(b[0]), "r"(b[1]));
}

// ---------------- prep: weight split + BN folding (double-precision constants) ----
__global__ void prep_kernel(const float* __restrict__ fc1_w, const float* __restrict__ fc2_w,
                            const float* __restrict__ bn1_g, const float* __restrict__ bn1_b,
                            const float* __restrict__ bn1_m, const float* __restrict__ bn1_v,
                            const float* __restrict__ bn2_g, const float* __restrict__ bn2_b,
                            const float* __restrict__ bn2_m, const float* __restrict__ bn2_v) {
  int i = blockIdx.x * blockDim.x + threadIdx.x;
  if (i < H_ * C_) {
    float w = fc1_w[i];
    __nv_bfloat16 hi = __float2bfloat16(w);
    float r1 = w - __bfloat162float(hi);
    __nv_bfloat16 mid = __float2bfloat16(r1);
    float r2 = r1 - __bfloat162float(mid);
    g_w1hi[i] = hi;
    g_w1mid[i] = mid;
    g_w1lo[i] = __float2bfloat16(r2);
    float w2 = fc2_w[i];
    __nv_bfloat16 hi2 = __float2bfloat16(w2);
    g_w2hi[i] = hi2;
    g_w2lo[i] = __float2bfloat16(w2 - __bfloat162float(hi2));
  }
  if (i < H_) {
    float vpe = bn1_v[i] + 1e-5f;
    float inv = (float)((double)bn1_g[i] / sqrt((double)vpe));
    g_inv1[i] = inv;
    g_add1[i] = bn1_b[i] - bn1_m[i] * inv;
  }
  if (i < C_) {
    float vpe = bn2_v[i] + 1e-5f;
    float inv = (float)((double)bn2_g[i] / sqrt((double)vpe));
    g_inv2[i] = inv;
    g_add2[i] = bn2_b[i] - bn2_m[i] * inv;
  }
}

// ---------------- stage 1: bn2 + LIF over T -> binary spikes (bf16) --------------
__global__ void lif1_kernel(const float* __restrict__ x) {
  int idx = blockIdx.x * blockDim.x + threadIdx.x;   // over B*C*N (exact grid)
  int n  = idx & (N_ - 1);
  int bc = idx >> 12;
  int c  = bc & (C_ - 1);
  float inv = g_inv2[c], add = g_add2[c];
  size_t base = (size_t)bc * L_ + n;
  float v = 0.0f;
#pragma unroll
  for (int t = 0; t < T_; t++) {
    float xt = x[base + t * N_] * inv + add;
    v = v + __fdiv_rn(xt - v, 1.5f);
    float s = (v >= 1.0f) ? 1.0f : 0.0f;
    g_s1[base + t * N_] = __float2bfloat16(s);
    v = (s != 0.0f) ? 0.0f : v;
  }
}

// ==================================================================================
// stage 2: fc1 GEMM (triple split, K=256 resident) + bias + bn1 + LIF fused
// Block 64(m) x 256(n), 8 warps (2m x 4n), warp tile 32x64.
// B tiles [k32][n256] triple-buffered (depth-3 cp.async, wait_group 1).
// ==================================================================================
#define F1_SA 264                       // A row stride (256 + 8), elements
#define F1_SB 264                       // B row stride (256 + 8), elements
#define F1_ASIZE (64 * F1_SA)           // per split, elements
#define F1_BSIZE (32 * F1_SB)           // per buffer, elements
#define F1_SMEM ((3 * F1_ASIZE + 3 * F1_BSIZE) * 2)

__global__ void __launch_bounds__(256, 1) fc1_lif_kernel(const float* __restrict__ fc1_b) {
  extern __shared__ __nv_bfloat16 sm1[];
  __nv_bfloat16* As = sm1;                    // [3][64][F1_SA]
  __nv_bfloat16* Bs = sm1 + 3 * F1_ASIZE;     // [3][32][F1_SB]

  const int tid = threadIdx.x;
  const int b = blockIdx.z, h0 = blockIdx.y * 64, n0 = blockIdx.x * 256;
  const int warp = tid >> 5, lane = tid & 31;
  const int wm = warp >> 2, wn = warp & 3;
  const int g = lane >> 2, tq = lane & 3;

  // ---- stage full-K A (hi, mid, lo) once via cp.async (joins group 0) ----
  {
    const __nv_bfloat16* srcs[3] = {g_w1hi, g_w1mid, g_w1lo};
#pragma unroll
    for (int s = 0; s < 3; s++)
#pragma unroll
      for (int i = 0; i < 8; i++) {
        int lin = tid + i * 256;              // 64 rows x 32 (16B) segs
        int r = lin >> 5, sg = lin & 31;
        cp16(smem_u32(&As[s * F1_ASIZE + r * F1_SA + sg * 8]),
             &srcs[s][(h0 + r) * C_ + sg * 8]);
      }
  }

  auto stageB = [&](int j, int buf) {
    int t = j >> 3, kt = j & 7;
    size_t base = (size_t)(b * C_ + kt * 32) * L_ + (size_t)t * N_ + n0;
#pragma unroll
    for (int i = 0; i < 4; i++) {
      int lin = tid + i * 256;                // 32 rows x 32 segs
      int r = lin >> 5, sg = lin & 31;
      cp16(smem_u32(&Bs[buf * F1_BSIZE + r * F1_SB + sg * 8]),
           &g_s1[base + (size_t)r * L_ + sg * 8]);
    }
  };

  stageB(0, 0);
  cp_commit();          // group: A + B0
  stageB(1, 1);
  cp_commit();          // group: B1

  float acc[2][8][4];
  float v[2][8][4];
#pragma unroll
  for (int mt = 0; mt < 2; mt++)
#pragma unroll
    for (int nt = 0; nt < 8; nt++)
#pragma unroll
      for (int q = 0; q < 4; q++) { acc[mt][nt][q] = 0.0f; v[mt][nt][q] = 0.0f; }

  const uint32_t a_base = smem_u32(&As[(wm * 32 + (lane & 15)) * F1_SA + (lane >> 4) * 8]);
  const uint32_t b_base = smem_u32(&Bs[(lane & 15) * F1_SB + wn * 64 + (lane >> 4) * 8]);

  int buf = 0;
#pragma unroll 1
  for (int j = 0; j < 32; j++) {
    cp_wait1();                       // stage j complete (j+1 may be in flight)
    __syncthreads();
    int nb = buf + 2; if (nb >= 3) nb -= 3;
    if (j + 2 < 32) stageB(j + 2, nb);
    cp_commit();                      // unconditional: keeps group accounting exact

    const int kt = j & 7;
#pragma unroll
    for (int ks = 0; ks < 2; ks++) {
      uint32_t bf[8][2];
#pragma unroll
      for (int p = 0; p < 4; p++) {
        uint32_t r[4];
        ldsmx4t(r, b_base + (uint32_t)(buf * F1_BSIZE + ks * 16 * F1_SB + p * 16) * 2);
        bf[2 * p][0] = r[0]; bf[2 * p][1] = r[1];
        bf[2 * p + 1][0] = r[2]; bf[2 * p + 1][1] = r[3];
      }
#pragma unroll
      for (int mt = 0; mt < 2; mt++)
#pragma unroll
        for (int s = 0; s < 3; s++) {
          uint32_t a[4];
          ldsmx4(a, a_base + (uint32_t)(s * F1_ASIZE + mt * 16 * F1_SA + kt * 32 + ks * 16) * 2);
#pragma unroll
          for (int nt = 0; nt < 8; nt++) mma16816(acc[mt][nt], a, bf[nt]);
        }
    }

    if ((j & 7) == 7) {            // end of one timestep: fused bias+bn1+LIF epilogue
      const int t = j >> 3;
#pragma unroll
      for (int mt = 0; mt < 2; mt++)
#pragma unroll
        for (int rr = 0; rr < 2; rr++) {
          int row = h0 + wm * 32 + mt * 16 + rr * 8 + g;
          float bias = fc1_b[row], inv = g_inv1[row], add = g_add1[row];
          size_t obase = (size_t)(b * H_ + row) * L_ + (size_t)t * N_;
#pragma unroll
          for (int nt = 0; nt < 8; nt++) {
            int col = n0 + wn * 64 + nt * 8 + tq * 2;
            float z0 = (acc[mt][nt][rr * 2 + 0] + bias) * inv + add;
            float z1 = (acc[mt][nt][rr * 2 + 1] + bias) * inv + add;
            float v0 = v[mt][nt][rr * 2 + 0];
            float v1 = v[mt][nt][rr * 2 + 1];
            v0 = v0 + __fdiv_rn(z0 - v0, 1.5f);
            v1 = v1 + __fdiv_rn(z1 - v1, 1.5f);
            float s0 = (v0 >= 1.0f) ? 1.0f : 0.0f;
            float s1 = (v1 >= 1.0f) ? 1.0f : 0.0f;
            v[mt][nt][rr * 2 + 0] = (s0 != 0.0f) ? 0.0f : v0;
            v[mt][nt][rr * 2 + 1] = (s1 != 0.0f) ? 0.0f : v1;
            __nv_bfloat162 sp;
            sp.x = __float2bfloat16(s0);
            sp.y = __float2bfloat16(s1);
            *(__nv_bfloat162*)&g_s2[obase + col] = sp;
            acc[mt][nt][rr * 2 + 0] = 0.0f;
            acc[mt][nt][rr * 2 + 1] = 0.0f;
          }
        }
    }
    buf = (buf == 2) ? 0 : buf + 1;
  }
}

// ==================================================================================
// stage 3: fc2 GEMM (double split) + bias -> fp32 output
// Block 64(m=c) x 256(n=l), 8 warps (2m x 4n), warp tile 32x64.
// A and B tiles triple-buffered (depth-3 cp.async, wait_group 1).
// ==================================================================================
#define F2_SA 40                        // A row stride (32 + 8), elements
#define F2_SB 264                       // B row stride (256 + 8), elements
#define F2_ABUF (2 * 64 * F2_SA)        // per buffer (2 splits), elements
#define F2_BBUF (32 * F2_SB)            // per buffer, elements
#define F2_SMEM ((3 * F2_ABUF + 3 * F2_BBUF) * 2)

__global__ void __launch_bounds__(256, 2) fc2_kernel(const float* __restrict__ fc2_b,
                                                     float* __restrict__ out) {
  extern __shared__ __nv_bfloat16 sm2[];
  __nv_bfloat16* As = sm2;                    // [3buf][2split][64][F2_SA]
  __nv_bfloat16* Bs = sm2 + 3 * F2_ABUF;      // [3buf][32][F2_SB]

  const int tid = threadIdx.x;
  const int b = blockIdx.z, c0 = blockIdx.y * 64, l0 = blockIdx.x * 256;
  const int warp = tid >> 5, lane = tid & 31;
  const int wm = warp >> 2, wn = warp & 3;
  const int g = lane >> 2, tq = lane & 3;

  auto stage = [&](int kt, int buf) {
    int r = tid >> 2, sg = tid & 3;           // A: 64 rows x 4 segs, per split
    cp16(smem_u32(&As[buf * F2_ABUF + r * F2_SA + sg * 8]),
         &g_w2hi[(c0 + r) * H_ + kt * 32 + sg * 8]);
    cp16(smem_u32(&As[buf * F2_ABUF + 64 * F2_SA + r * F2_SA + sg * 8]),
         &g_w2lo[(c0 + r) * H_ + kt * 32 + sg * 8]);
    size_t base = (size_t)(b * H_ + kt * 32) * L_ + l0;
#pragma unroll
    for (int i = 0; i < 4; i++) {
      int lin = tid + i * 256;                // B: 32 rows x 32 segs
      int rb = lin >> 5, sgb = lin & 31;
      cp16(smem_u32(&Bs[buf * F2_BBUF + rb * F2_SB + sgb * 8]),
           &g_s2[base + (size_t)rb * L_ + sgb * 8]);
    }
  };

  stage(0, 0);
  cp_commit();
  stage(1, 1);
  cp_commit();

  float acc[2][8][4];
#pragma unroll
  for (int mt = 0; mt < 2; mt++)
#pragma unroll
    for (int nt = 0; nt < 8; nt++)
#pragma unroll
      for (int q = 0; q < 4; q++) acc[mt][nt][q] = 0.0f;

  const uint32_t a_base = smem_u32(&As[(wm * 32 + (lane & 15)) * F2_SA + (lane >> 4) * 8]);
  const uint32_t b_base = smem_u32(&Bs[(lane & 15) * F2_SB + wn * 64 + (lane >> 4) * 8]);

  int buf = 0;
#pragma unroll 1
  for (int j = 0; j < 32; j++) {
    cp_wait1();
    __syncthreads();
    int nb = buf + 2; if (nb >= 3) nb -= 3;
    if (j + 2 < 32) stage(j + 2, nb);
    cp_commit();

#pragma unroll
    for (int ks = 0; ks < 2; ks++) {
      uint32_t bf[8][2];
#pragma unroll
      for (int p = 0; p < 4; p++) {
        uint32_t r[4];
        ldsmx4t(r, b_base + (uint32_t)(buf * F2_BBUF + ks * 16 * F2_SB + p * 16) * 2);
        bf[2 * p][0] = r[0]; bf[2 * p][1] = r[1];
        bf[2 * p + 1][0] = r[2]; bf[2 * p + 1][1] = r[3];
      }
#pragma unroll
      for (int mt = 0; mt < 2; mt++)
#pragma unroll
        for (int s = 0; s < 2; s++) {
          uint32_t a[4];
          ldsmx4(a, a_base + (uint32_t)(buf * F2_ABUF + s * 64 * F2_SA + mt * 16 * F2_SA + ks * 16) * 2);
#pragma unroll
          for (int nt = 0; nt < 8; nt++) mma16816(acc[mt][nt], a, bf[nt]);
        }
    }
    buf = (buf == 2) ? 0 : buf + 1;
  }

  // epilogue: bias + coalesced float2 stores
#pragma unroll
  for (int mt = 0; mt < 2; mt++)
#pragma unroll
    for (int rr = 0; rr < 2; rr++) {
      int row = c0 + wm * 32 + mt * 16 + rr * 8 + g;
      float bias = fc2_b[row];
      size_t obase = (size_t)(b * C_ + row) * L_ + l0;
#pragma unroll
      for (int nt = 0; nt < 8; nt++) {
        int col = wn * 64 + nt * 8 + tq * 2;
        float2 o;
        o.x = acc[mt][nt][rr * 2 + 0] + bias;
        o.y = acc[mt][nt][rr * 2 + 1] + bias;
        *(float2*)&out[obase + col] = o;
      }
    }
}

// ---------------- launch ----------------------------------------------------------
extern "C" void kernel_launch(void* const* d_in, const int* in_sizes, int n_in,
                              void* d_out, int out_size) {
  (void)in_sizes; (void)n_in; (void)out_size;
  const float* x      = (const float*)d_in[0];
  const float* fc1_w  = (const float*)d_in[1];
  const float* fc1_b  = (const float*)d_in[2];
  const float* fc2_w  = (const float*)d_in[3];
  const float* fc2_b  = (const float*)d_in[4];
  const float* bn1_g  = (const float*)d_in[5];
  const float* bn1_bt = (const float*)d_in[6];
  const float* bn1_m  = (const float*)d_in[7];
  const float* bn1_v  = (const float*)d_in[8];
  const float* bn2_g  = (const float*)d_in[9];
  const float* bn2_bt = (const float*)d_in[10];
  const float* bn2_m  = (const float*)d_in[11];
  const float* bn2_v  = (const float*)d_in[12];
  float* out = (float*)d_out;

  prep_kernel<<<(H_ * C_) / 256, 256>>>(fc1_w, fc2_w, bn1_g, bn1_bt, bn1_m, bn1_v,
                                        bn2_g, bn2_bt, bn2_m, bn2_v);
  lif1_kernel<<<(B_ * C_ * N_) / 256, 256>>>(x);

  static bool attr_set = false;
  if (!attr_set) {
    cudaFuncSetAttribute(fc1_lif_kernel, cudaFuncAttributeMaxDynamicSharedMemorySize, F1_SMEM);
    cudaFuncSetAttribute(fc2_kernel, cudaFuncAttributeMaxDynamicSharedMemorySize, F2_SMEM);
    attr_set = true;
  }

  dim3 g2(N_ / 256, H_ / 64, B_);
  fc1_lif_kernel<<<g2, 256, F1_SMEM>>>(fc1_b);

  dim3 g3(L_ / 256, C_ / 64, B_);
  fc2_kernel<<<g3, 256, F2_SMEM>>>(fc2_b, out);
}